// round 1
// baseline (speedup 1.0000x reference)
#include <cuda_runtime.h>

#define BB 8192
#define TT 256
#define HH 10

// Scratch (no allocations allowed): transposed x with one padded row for the
// branchless t+1 prefetch, plus packed/sampled/pre-scaled weights.
__device__ float g_xT[(TT + 1) * BB];
__device__ float g_whh[400];   // [q][j][k] = S_q * w_hh[j][10q+k]
__device__ float g_wih[40];    // [q][k]    = S_q * w_ih[0][10q+k]
__device__ float g_bb[40];     // [q][k]    = S_q * b[10q+k]

__device__ __forceinline__ float ex2f(float x) {
    float y; asm("ex2.approx.f32 %0, %1;" : "=f"(y) : "f"(x)); return y;
}
__device__ __forceinline__ float rcpf(float x) {
    float y; asm("rcp.approx.f32 %0, %1;" : "=f"(y) : "f"(x)); return y;
}

// ---------------------------------------------------------------------------
// Setup: sample variational weights (w = mu + softplus(rho)*eps) and repack
// with the per-gate-block activation pre-scale folded in.
//   q in {0,1,3} (i,f,o -> sigmoid): S = -log2(e)
//   q == 2       (g   -> tanh)     : S = -2*log2(e)
// ---------------------------------------------------------------------------
__global__ void setup_kernel(const float* __restrict__ wih_mu, const float* __restrict__ wih_rho,
                             const float* __restrict__ whh_mu, const float* __restrict__ whh_rho,
                             const float* __restrict__ b_mu,   const float* __restrict__ b_rho,
                             const float* __restrict__ eps_ih, const float* __restrict__ eps_hh,
                             const float* __restrict__ eps_b)
{
    const float L2E = 1.4426950408889634f;
    int tid = threadIdx.x;
    if (tid < 40) {
        int g = tid, q = g / 10, k = g % 10;
        float S = (q == 2) ? (-2.f * L2E) : (-L2E);
        float w = wih_mu[g] + log1pf(expf(wih_rho[g])) * eps_ih[g];
        g_wih[q * 10 + k] = S * w;
        float b = b_mu[g] + log1pf(expf(b_rho[g])) * eps_b[g];
        g_bb[q * 10 + k] = S * b;
    }
    for (int idx = tid; idx < 400; idx += blockDim.x) {
        int j = idx / 40, g = idx % 40, q = g / 10, k = g % 10;
        float S = (q == 2) ? (-2.f * L2E) : (-L2E);
        float w = whh_mu[idx] + log1pf(expf(whh_rho[idx])) * eps_hh[idx];
        g_whh[q * 100 + j * 10 + k] = S * w;
    }
}

// ---------------------------------------------------------------------------
// Transpose x: (B, T) -> (T, B) so the hot loop reads one 32B sector / warp.
// ---------------------------------------------------------------------------
__global__ void transpose_kernel(const float* __restrict__ x)
{
    __shared__ float tile[32][33];
    int t0 = blockIdx.x * 32, b0 = blockIdx.y * 32;
    int tx = threadIdx.x, ty = threadIdx.y;
#pragma unroll
    for (int i = ty; i < 32; i += 8)
        tile[i][tx] = x[(size_t)(b0 + i) * TT + t0 + tx];
    __syncthreads();
#pragma unroll
    for (int i = ty; i < 32; i += 8)
        g_xT[(size_t)(t0 + i) * BB + b0 + tx] = tile[tx][i];
}

// Zero the padding row read by the branchless prefetch at t = T-1.
__global__ void pad_kernel()
{
    int i = blockIdx.x * blockDim.x + threadIdx.x;
    if (i < BB) g_xT[(size_t)TT * BB + i] = 0.f;
}

// ---------------------------------------------------------------------------
// Main recurrence. 4 lanes per batch element (lane q owns gate block q:
// q0=i, q1=f, q2=g, q3=o), 8 batch elements per warp, 1 warp per block
// (1024 blocks -> ~7 resident warps/SM, balanced across 148 SMs).
// Each lane keeps its 100 w_hh weights in registers. All 4 lanes receive
// i,f,g,o via width-4 shuffles and redundantly maintain identical (c,h).
// c is stored pre-scaled: c2 = -2*log2(e)*c, so tanh(c) = 2*rcp(1+ex2(c2))-1.
// ---------------------------------------------------------------------------
__global__ void __launch_bounds__(32)
lstm_kernel(const float* __restrict__ lin_w, const float* __restrict__ lin_b,
            float* __restrict__ out)
{
    const float L2E = 1.4426950408889634f;
    int lane  = threadIdx.x;
    int q     = lane & 3;
    int batch = blockIdx.x * 8 + (lane >> 2);

    // Load this lane's recurrent weights into registers (one-time).
    float w[100];
    const float4* wp = reinterpret_cast<const float4*>(g_whh + q * 100);
#pragma unroll
    for (int i = 0; i < 25; i++) {
        float4 v = wp[i];
        w[4 * i] = v.x; w[4 * i + 1] = v.y; w[4 * i + 2] = v.z; w[4 * i + 3] = v.w;
    }
    float wih[10], bb[10];
#pragma unroll
    for (int k = 0; k < 10; k++) { wih[k] = g_wih[q * 10 + k]; bb[k] = g_bb[q * 10 + k]; }

    // Unified activation: act = fma(A, rcp(1 + ex2(acc)), D)
    //   sigmoid lanes: A=1, D=0   (acc already pre-scaled by -log2 e)
    //   g lane: act = -2*log2(e)*tanh(z) = fma(-4*L2E, r, 2*L2E)  (c2-ready form)
    float A = (q == 2) ? (-4.f * L2E) : 1.f;
    float D = (q == 2) ? ( 2.f * L2E) : 0.f;

    float h[10], c2[10];
#pragma unroll
    for (int k = 0; k < 10; k++) { h[k] = 0.f; c2[k] = 0.f; }

    const float* xp = g_xT + batch;
    float xv = xp[0];

#pragma unroll 1
    for (int t = 0; t < TT; t++) {
        xp += BB;
        float xn = *xp;  // prefetch next timestep (padded row at t = T-1)

        // gates: acc = S_q * (x*w_ih + b + h @ w_hh) for this lane's 10 gates
        float acc[10];
#pragma unroll
        for (int k = 0; k < 10; k++) acc[k] = fmaf(xv, wih[k], bb[k]);
#pragma unroll
        for (int j = 0; j < 10; j++) {
            float hj = h[j];
#pragma unroll
            for (int k = 0; k < 10; k++) acc[k] = fmaf(hj, w[j * 10 + k], acc[k]);
        }

        // activations (2 MUFU + 2 fma-pipe per gate)
        float act[10];
#pragma unroll
        for (int k = 0; k < 10; k++) {
            float e = ex2f(acc[k]);
            float r = rcpf(1.f + e);
            act[k] = fmaf(A, r, D);
        }

        // exchange i,f,g,o within the 4-lane group; all lanes update (c2, h)
#pragma unroll
        for (int k = 0; k < 10; k++) {
            float ik = __shfl_sync(0xffffffffu, act[k], 0, 4);
            float fk = __shfl_sync(0xffffffffu, act[k], 1, 4);
            float gk = __shfl_sync(0xffffffffu, act[k], 2, 4);  // = -2*L2E*tanh(g_raw)
            float ok = __shfl_sync(0xffffffffu, act[k], 3, 4);
            c2[k] = fmaf(fk, c2[k], ik * gk);
            float e  = ex2f(c2[k]);                 // = exp(-2c)
            float tc = fmaf(2.f, rcpf(1.f + e), -1.f);  // tanh(c)
            h[k] = ok * tc;
        }
        xv = xn;
    }

    // linear head: out[b] = h . lin_w + lin_b   (one lane per batch writes)
    if (q == 0) {
        float s = lin_b[0];
#pragma unroll
        for (int k = 0; k < 10; k++) s = fmaf(h[k], lin_w[k], s);
        out[batch] = s;
    }
}

extern "C" void kernel_launch(void* const* d_in, const int* in_sizes, int n_in,
                              void* d_out, int out_size)
{
    const float* x       = (const float*)d_in[0];
    const float* wih_mu  = (const float*)d_in[1];
    const float* wih_rho = (const float*)d_in[2];
    const float* whh_mu  = (const float*)d_in[3];
    const float* whh_rho = (const float*)d_in[4];
    const float* b_mu    = (const float*)d_in[5];
    const float* b_rho   = (const float*)d_in[6];
    const float* eps_ih  = (const float*)d_in[7];
    const float* eps_hh  = (const float*)d_in[8];
    const float* eps_b   = (const float*)d_in[9];
    const float* lin_w   = (const float*)d_in[10];
    const float* lin_b   = (const float*)d_in[11];
    float* out = (float*)d_out;

    setup_kernel<<<1, 512>>>(wih_mu, wih_rho, whh_mu, whh_rho,
                             b_mu, b_rho, eps_ih, eps_hh, eps_b);
    transpose_kernel<<<dim3(TT / 32, BB / 32), dim3(32, 8)>>>(x);
    pad_kernel<<<BB / 256, 256>>>();
    lstm_kernel<<<BB / 8, 32>>>(lin_w, lin_b, out);
}

// round 2
// speedup vs baseline: 1.6117x; 1.6117x over previous
#include <cuda_runtime.h>

#define BB 8192
#define TT 256
#define HH 10

// Scratch (no allocations allowed): transposed x with one padded row for the
// branchless t+1 prefetch, plus packed/sampled/pre-scaled weights.
__device__ float g_xT[(TT + 1) * BB];
__device__ float g_whh[400];   // [q][j][k] = S_q * w_hh[j][10q+k]
__device__ float g_wih[40];    // [q][k]    = S_q * w_ih[0][10q+k]
__device__ float g_bb[40];     // [q][k]    = S_q * b[10q+k]

__device__ __forceinline__ float tanh_approx(float x) {
    float y; asm("tanh.approx.f32 %0, %1;" : "=f"(y) : "f"(x)); return y;
}
__device__ __forceinline__ unsigned long long pk2(float lo, float hi) {
    unsigned long long r;
    asm("mov.b64 %0, {%1, %2};" : "=l"(r) : "f"(lo), "f"(hi));
    return r;
}
__device__ __forceinline__ void upk2(float& lo, float& hi, unsigned long long v) {
    asm("mov.b64 {%0, %1}, %2;" : "=f"(lo), "=f"(hi) : "l"(v));
}
__device__ __forceinline__ unsigned long long fma2(unsigned long long a,
                                                   unsigned long long b,
                                                   unsigned long long c) {
    unsigned long long d;
    asm("fma.rn.f32x2 %0, %1, %2, %3;" : "=l"(d) : "l"(a), "l"(b), "l"(c));
    return d;
}

// ---------------------------------------------------------------------------
// Setup: sample variational weights (w = mu + softplus(rho)*eps) and repack
// with the sigmoid half-angle pre-scale folded in:
//   q in {0,1,3} (i,f,o -> sigmoid): S = 0.5   (sigmoid(z) = 0.5*tanh(z/2)+0.5)
//   q == 2       (g   -> tanh)     : S = 1.0
// ---------------------------------------------------------------------------
__global__ void setup_kernel(const float* __restrict__ wih_mu, const float* __restrict__ wih_rho,
                             const float* __restrict__ whh_mu, const float* __restrict__ whh_rho,
                             const float* __restrict__ b_mu,   const float* __restrict__ b_rho,
                             const float* __restrict__ eps_ih, const float* __restrict__ eps_hh,
                             const float* __restrict__ eps_b)
{
    int tid = threadIdx.x;
    if (tid < 40) {
        int g = tid, q = g / 10, k = g % 10;
        float S = (q == 2) ? 1.f : 0.5f;
        float w = wih_mu[g] + log1pf(expf(wih_rho[g])) * eps_ih[g];
        g_wih[q * 10 + k] = S * w;
        float b = b_mu[g] + log1pf(expf(b_rho[g])) * eps_b[g];
        g_bb[q * 10 + k] = S * b;
    }
    for (int idx = tid; idx < 400; idx += blockDim.x) {
        int j = idx / 40, g = idx % 40, q = g / 10, k = g % 10;
        float S = (q == 2) ? 1.f : 0.5f;
        float w = whh_mu[idx] + log1pf(expf(whh_rho[idx])) * eps_hh[idx];
        g_whh[q * 100 + j * 10 + k] = S * w;
    }
}

// ---------------------------------------------------------------------------
// Transpose x: (B, T) -> (T, B) so the hot loop reads one 32B sector / warp.
// ---------------------------------------------------------------------------
__global__ void transpose_kernel(const float* __restrict__ x)
{
    __shared__ float tile[32][33];
    int t0 = blockIdx.x * 32, b0 = blockIdx.y * 32;
    int tx = threadIdx.x, ty = threadIdx.y;
#pragma unroll
    for (int i = ty; i < 32; i += 8)
        tile[i][tx] = x[(size_t)(b0 + i) * TT + t0 + tx];
    __syncthreads();
#pragma unroll
    for (int i = ty; i < 32; i += 8)
        g_xT[(size_t)(t0 + i) * BB + b0 + tx] = tile[tx][i];
}

// Zero the padding row read by the branchless prefetch at t = T-1.
__global__ void pad_kernel()
{
    int i = blockIdx.x * blockDim.x + threadIdx.x;
    if (i < BB) g_xT[(size_t)TT * BB + i] = 0.f;
}

// ---------------------------------------------------------------------------
// Main recurrence. 4 lanes per batch element (lane q owns gate block q:
// q0=i, q1=f, q2=g, q3=o), 8 batch elements per warp, 1 warp per block.
// Each lane keeps its 100 w_hh weights in registers as 50 f32x2 pairs; the
// 10x10 recurrent GEMM runs on fma.rn.f32x2 (55 packed FMAs + 10 hj packs).
// Activations use the hw MUFU tanh: sigmoid(z) = 0.5*tanh(z/2)+0.5 with the
// 0.5 pre-folded into the weights. All 4 lanes receive i,f,g,o via width-4
// shuffles and redundantly maintain identical (c,h).
// ---------------------------------------------------------------------------
__global__ void __launch_bounds__(32)
lstm_kernel(const float* __restrict__ lin_w, const float* __restrict__ lin_b,
            float* __restrict__ out)
{
    int lane  = threadIdx.x;
    int q     = lane & 3;
    int batch = blockIdx.x * 8 + (lane >> 2);

    // Load this lane's recurrent weights as packed f32x2 pairs (one-time).
    // k-adjacent floats at 8B-aligned offsets -> direct 64-bit loads.
    unsigned long long w2[50], wih2[5], bb2[5];
    {
        const unsigned long long* wp = reinterpret_cast<const unsigned long long*>(g_whh + q * 100);
#pragma unroll
        for (int i = 0; i < 50; i++) w2[i] = wp[i];
        const unsigned long long* ip = reinterpret_cast<const unsigned long long*>(g_wih + q * 10);
        const unsigned long long* bp = reinterpret_cast<const unsigned long long*>(g_bb + q * 10);
#pragma unroll
        for (int p = 0; p < 5; p++) { wih2[p] = ip[p]; bb2[p] = bp[p]; }
    }

    // act = fma(A, tanh(acc), D): sigmoid lanes A=0.5,D=0.5 ; g lane A=1,D=0
    float A = (q == 2) ? 1.f : 0.5f;
    float D = (q == 2) ? 0.f : 0.5f;

    float h[10], c[10];
#pragma unroll
    for (int k = 0; k < 10; k++) { h[k] = 0.f; c[k] = 0.f; }

    const float* xp = g_xT + batch;
    float xv = xp[0];

#pragma unroll 1
    for (int t = 0; t < TT; t++) {
        xp += BB;
        float xn = *xp;  // prefetch next timestep (padded row at t = T-1)

        // gates: acc = S_q * (x*w_ih + b + h @ w_hh), 2 gates per f32x2 reg
        unsigned long long xx = pk2(xv, xv);
        unsigned long long acc2[5];
#pragma unroll
        for (int p = 0; p < 5; p++) acc2[p] = fma2(xx, wih2[p], bb2[p]);
#pragma unroll
        for (int j = 0; j < 10; j++) {
            unsigned long long hj = pk2(h[j], h[j]);
#pragma unroll
            for (int p = 0; p < 5; p++) acc2[p] = fma2(hj, w2[j * 5 + p], acc2[p]);
        }

        // activations: 1 MUFU tanh + 1 FMA per gate
        float act[10];
#pragma unroll
        for (int p = 0; p < 5; p++) {
            float a0, a1; upk2(a0, a1, acc2[p]);
            act[2 * p]     = fmaf(A, tanh_approx(a0), D);
            act[2 * p + 1] = fmaf(A, tanh_approx(a1), D);
        }

        // exchange i,f,g,o within the 4-lane group; all lanes update (c, h)
#pragma unroll
        for (int k = 0; k < 10; k++) {
            float ik = __shfl_sync(0xffffffffu, act[k], 0, 4);
            float fk = __shfl_sync(0xffffffffu, act[k], 1, 4);
            float gk = __shfl_sync(0xffffffffu, act[k], 2, 4);
            float ok = __shfl_sync(0xffffffffu, act[k], 3, 4);
            c[k] = fmaf(fk, c[k], ik * gk);
            h[k] = ok * tanh_approx(c[k]);
        }
        xv = xn;
    }

    // linear head: out[b] = h . lin_w + lin_b   (one lane per batch writes)
    if (q == 0) {
        float s = lin_b[0];
#pragma unroll
        for (int k = 0; k < 10; k++) s = fmaf(h[k], lin_w[k], s);
        out[batch] = s;
    }
}

extern "C" void kernel_launch(void* const* d_in, const int* in_sizes, int n_in,
                              void* d_out, int out_size)
{
    const float* x       = (const float*)d_in[0];
    const float* wih_mu  = (const float*)d_in[1];
    const float* wih_rho = (const float*)d_in[2];
    const float* whh_mu  = (const float*)d_in[3];
    const float* whh_rho = (const float*)d_in[4];
    const float* b_mu    = (const float*)d_in[5];
    const float* b_rho   = (const float*)d_in[6];
    const float* eps_ih  = (const float*)d_in[7];
    const float* eps_hh  = (const float*)d_in[8];
    const float* eps_b   = (const float*)d_in[9];
    const float* lin_w   = (const float*)d_in[10];
    const float* lin_b   = (const float*)d_in[11];
    float* out = (float*)d_out;

    setup_kernel<<<1, 512>>>(wih_mu, wih_rho, whh_mu, whh_rho,
                             b_mu, b_rho, eps_ih, eps_hh, eps_b);
    transpose_kernel<<<dim3(TT / 32, BB / 32), dim3(32, 8)>>>(x);
    pad_kernel<<<BB / 256, 256>>>();
    lstm_kernel<<<BB / 8, 32>>>(lin_w, lin_b, out);
}